// round 9
// baseline (speedup 1.0000x reference)
#include <cuda_runtime.h>
#include <math.h>

#define B_   8192
#define L_   200
#define S_   81
#define SP_  84        /* padded row stride (floats) */
#define CEN_ 40
#define D_   128
#define H_   4
#define XSZ  (L_*S_)   /* 16200 floats per b */

// ---- scratch (device globals; no allocation allowed) ----
__device__ float g_R[(size_t)B_*H_*L_];
__device__ float g_c[(size_t)B_*H_];
__device__ float g_central[(size_t)B_*D_];
__device__ float g_Y[(size_t)B_*H_*L_];
__device__ float g_dummy;

// 3 no-op launches shift ncu -s 5 window onto kprep (slot 6)
__global__ void knop() { if (threadIdx.x == 0) g_dummy = 1.0f; }

// ============================================================
// kprep v2 (unchanged): 32-b tiles, grid 256. Q, central, R, c.
// block 256, dyn smem = 19968 floats (79872 B)
// ============================================================
__global__ void __launch_bounds__(256, 2) kprep(
    const float* __restrict__ x,  const float* __restrict__ Wk,
    const float* __restrict__ bk, const float* __restrict__ Wv,
    const float* __restrict__ bv, const float* __restrict__ Wq,
    const float* __restrict__ bq)
{
    extern __shared__ float sm[];
    float* XcT = sm;           // [200][32]
    float* Wb  = sm + 6400;    // [256][53]
    const int tid = threadIdx.x;
    const int b0  = blockIdx.x * 32;

    for (int idx = tid; idx < 32 * 200; idx += 256) {
        int bb = idx & 31, l = idx >> 5;
        XcT[l * 32 + bb] = x[(size_t)(b0 + bb) * XSZ + l * S_ + CEN_];
    }
    __syncthreads();

    const int bi = tid & 3;
    const int dj = tid >> 2;
    float acc[8][4];
    #pragma unroll
    for (int v = 0; v < 8; v++)
        #pragma unroll
        for (int u = 0; u < 4; u++) acc[v][u] = 0.f;

    const int w = tid >> 5, lane = tid & 31;
    for (int k0 = 0; k0 < 200; k0 += 50) {
        for (int r = 0; r < 32; r++) {
            int dd = w * 32 + r;
            const float* wr = (dd < 128) ? (Wq + dd * L_) : (Wv + (size_t)(dd - 128) * L_);
            Wb[dd * 53 + lane] = wr[k0 + lane];
            if (lane < 18) Wb[dd * 53 + 32 + lane] = wr[k0 + 32 + lane];
        }
        __syncthreads();
        #pragma unroll 2
        for (int kk = 0; kk < 50; kk++) {
            float4 xa0 = *(const float4*)&XcT[(k0 + kk) * 32 + bi * 8];
            float4 xa1 = *(const float4*)&XcT[(k0 + kk) * 32 + bi * 8 + 4];
            float xa[8] = {xa0.x, xa0.y, xa0.z, xa0.w, xa1.x, xa1.y, xa1.z, xa1.w};
            float wv4[4];
            #pragma unroll
            for (int u = 0; u < 4; u++) wv4[u] = Wb[(dj * 4 + u) * 53 + kk];
            #pragma unroll
            for (int v = 0; v < 8; v++)
                #pragma unroll
                for (int u = 0; u < 4; u++)
                    acc[v][u] += xa[v] * wv4[u];
        }
        __syncthreads();
    }

    float* QT = sm;  // [128][32]
    if (dj < 32) {
        #pragma unroll
        for (int u = 0; u < 4; u++) {
            int d = dj * 4 + u;
            float bqd = bq[d];
            #pragma unroll
            for (int v = 0; v < 8; v++)
                QT[d * 32 + bi * 8 + v] = acc[v][u] + bqd;
        }
    } else {
        #pragma unroll
        for (int u = 0; u < 4; u++) {
            int d = (dj - 32) * 4 + u;
            float bvd = bv[d];
            #pragma unroll
            for (int v = 0; v < 8; v++)
                g_central[(size_t)(b0 + bi * 8 + v) * D_ + d] = acc[v][u] + bvd;
        }
    }
    __syncthreads();

    if (tid < 128) {
        int bb = tid & 31, h = tid >> 5;
        float cacc = 0.f;
        for (int dd = 0; dd < 32; dd++)
            cacc += QT[(h * 32 + dd) * 32 + bb] * bk[h * 32 + dd];
        g_c[(size_t)(b0 + bb) * H_ + h] = cacc;
    }

    float* Wkc = sm + 4096;    // [128][100]
    const int bg = w & 3;
    const int hp = w >> 2;
    for (int lc = 0; lc < 2; lc++) {
        __syncthreads();
        for (int idx = tid; idx < 12800; idx += 256) {
            int dd = idx / 100, ll = idx - dd * 100;
            Wkc[idx] = Wk[(size_t)dd * L_ + lc * 100 + ll];
        }
        __syncthreads();
        #pragma unroll
        for (int hh = 0; hh < 2; hh++) {
            const int h = hp * 2 + hh;
            float acc2[8][4];
            #pragma unroll
            for (int v = 0; v < 8; v++)
                #pragma unroll
                for (int jj = 0; jj < 4; jj++) acc2[v][jj] = 0.f;
            for (int d = 0; d < 32; d++) {
                float4 q0 = *(const float4*)&QT[(h * 32 + d) * 32 + bg * 8];
                float4 q1 = *(const float4*)&QT[(h * 32 + d) * 32 + bg * 8 + 4];
                float q8[8] = {q0.x, q0.y, q0.z, q0.w, q1.x, q1.y, q1.z, q1.w};
                float wk4[4];
                #pragma unroll
                for (int jj = 0; jj < 4; jj++) {
                    int ll = lane + 32 * jj;
                    wk4[jj] = (ll < 100) ? Wkc[(h * 32 + d) * 100 + ll] : 0.f;
                }
                #pragma unroll
                for (int v = 0; v < 8; v++)
                    #pragma unroll
                    for (int jj = 0; jj < 4; jj++)
                        acc2[v][jj] += q8[v] * wk4[jj];
            }
            #pragma unroll
            for (int jj = 0; jj < 4; jj++) {
                int ll = lane + 32 * jj;
                if (ll < 100) {
                    int l = lc * 100 + ll;
                    #pragma unroll
                    for (int v = 0; v < 8; v++)
                        g_R[(size_t)(b0 + bg * 8 + v) * (H_ * L_) + h * L_ + l] = acc2[v][jj];
                }
            }
        }
    }
}

// ============================================================
// kmain (R7 exact): 384 threads, 3 CTAs/SM.
// dyn smem = 17940 floats (71760 B)
// ============================================================
__global__ void __launch_bounds__(384, 3) kmain(const float* __restrict__ x)
{
    extern __shared__ float sm[];
    float* xs = sm;            // [200][84]
    float* Rs = sm + 16800;    // [4][200]
    float* cs = Rs + 800;      // [4]
    float* sc = cs + 4;        // [4][84]
    const int tid = threadIdx.x;
    const size_t b = blockIdx.x;

    {
        const float* xg = x + b * XSZ + tid;
        int l = tid / 81;
        int s = tid - l * 81;
        int off = l * SP_ + s;
        #pragma unroll 6
        for (int it = 0; it < 42; ++it) {
            xs[off] = xg[it * 384];
            s += 60;
            if (s >= 81) { s -= 81; off += 399; }
            else         {           off += 396; }
        }
        if (tid < 72) xs[off] = xg[42 * 384];

        if (tid < 200) {
            xs[tid * SP_ + 81] = 0.f;
            xs[tid * SP_ + 82] = 0.f;
            xs[tid * SP_ + 83] = 0.f;
        }
        for (int i = tid; i < 800; i += 384)
            Rs[i] = g_R[b * 800 + i];
        if (tid < 4) cs[tid] = g_c[b * 4 + tid];
    }
    __syncthreads();

    if (tid < 96) {
        const int sq = tid >> 2;
        const int c  = tid & 3;
        const int s4 = (sq < 21) ? sq * 4 : 80;
        const float* xp = xs + c * 50 * SP_ + s4;
        const float* r0p = Rs + c * 50;
        float a[H_][4];
        #pragma unroll
        for (int h = 0; h < H_; h++)
            #pragma unroll
            for (int j = 0; j < 4; j++) a[h][j] = 0.f;
        #pragma unroll 5
        for (int l = 0; l < 50; l++) {
            float4 xv = *(const float4*)xp;
            float r0 = r0p[l], r1 = r0p[200 + l], r2 = r0p[400 + l], r3 = r0p[600 + l];
            a[0][0] += r0 * xv.x; a[0][1] += r0 * xv.y; a[0][2] += r0 * xv.z; a[0][3] += r0 * xv.w;
            a[1][0] += r1 * xv.x; a[1][1] += r1 * xv.y; a[1][2] += r1 * xv.z; a[1][3] += r1 * xv.w;
            a[2][0] += r2 * xv.x; a[2][1] += r2 * xv.y; a[2][2] += r2 * xv.z; a[2][3] += r2 * xv.w;
            a[3][0] += r3 * xv.x; a[3][1] += r3 * xv.y; a[3][2] += r3 * xv.z; a[3][3] += r3 * xv.w;
            xp += SP_;
        }
        const unsigned m = 0xffffffffu;
        #pragma unroll
        for (int h = 0; h < H_; h++)
            #pragma unroll
            for (int j = 0; j < 4; j++) {
                a[h][j] += __shfl_xor_sync(m, a[h][j], 1);
                a[h][j] += __shfl_xor_sync(m, a[h][j], 2);
            }
        if (c == 0 && sq < 21) {
            #pragma unroll
            for (int h = 0; h < H_; h++) {
                float ch = cs[h];
                float4 o;
                float* op = (float*)&o;
                #pragma unroll
                for (int j = 0; j < 4; j++) {
                    int s = sq * 4 + j;
                    float v = (a[h][j] + ch) * 0.0883883476483184405f;
                    if (s == CEN_) v += -1000000.0f;
                    if (s >= 81)  v = -INFINITY;
                    op[j] = v;
                }
                *(float4*)&sc[h * SP_ + sq * 4] = o;
            }
        }
    }
    __syncthreads();

    const int wid = tid >> 5, lane = tid & 31;
    if (wid < 4) {
        float v0 = sc[wid * SP_ + lane];
        float v1 = sc[wid * SP_ + 32 + lane];
        float v2 = (lane < 20) ? sc[wid * SP_ + 64 + lane] : -INFINITY;
        float mx = fmaxf(v0, fmaxf(v1, v2));
        #pragma unroll
        for (int o = 16; o > 0; o >>= 1) mx = fmaxf(mx, __shfl_xor_sync(0xffffffffu, mx, o));
        float e0 = __expf(v0 - mx), e1 = __expf(v1 - mx);
        float e2 = (lane < 20 && v2 > -INFINITY) ? __expf(v2 - mx) : 0.f;
        float s3 = e0 + e1 + e2;
        #pragma unroll
        for (int o = 16; o > 0; o >>= 1) s3 += __shfl_xor_sync(0xffffffffu, s3, o);
        float rs = 1.f / s3;
        sc[wid * SP_ + lane] = e0 * rs;
        sc[wid * SP_ + 32 + lane] = e1 * rs;
        if (lane < 20) sc[wid * SP_ + 64 + lane] = e2 * rs;
    }
    __syncthreads();

    if (tid < 200) {
        const float* xr = xs + tid * SP_;
        float a0 = 0.f, a1 = 0.f, a2 = 0.f, a3 = 0.f;
        #pragma unroll 7
        for (int c = 0; c < 21; c++) {
            float4 xv = *(const float4*)&xr[c * 4];
            float4 t0 = *(const float4*)&sc[0 * SP_ + c * 4];
            float4 t1 = *(const float4*)&sc[1 * SP_ + c * 4];
            float4 t2 = *(const float4*)&sc[2 * SP_ + c * 4];
            float4 t3 = *(const float4*)&sc[3 * SP_ + c * 4];
            a0 += t0.x * xv.x + t0.y * xv.y + t0.z * xv.z + t0.w * xv.w;
            a1 += t1.x * xv.x + t1.y * xv.y + t1.z * xv.z + t1.w * xv.w;
            a2 += t2.x * xv.x + t2.y * xv.y + t2.z * xv.z + t2.w * xv.w;
            a3 += t3.x * xv.x + t3.y * xv.y + t3.z * xv.z + t3.w * xv.w;
        }
        float* Yb = g_Y + b * 800;
        Yb[tid] = a0; Yb[200 + tid] = a1; Yb[400 + tid] = a2; Yb[600 + tid] = a3;
    }
}

// ============================================================
// ksurgate: fused surround + gate + output. grid 128, block 256.
// sur kept in registers (sur[8][4] per thread); kills g_sur.
// dyn smem = 32*201*4 = 25728 B
// ============================================================
__global__ void __launch_bounds__(256) ksurgate(
    const float* __restrict__ Wv, const float* __restrict__ bv,
    const float* __restrict__ Wg, const float* __restrict__ bg,
    float* __restrict__ out)
{
    extern __shared__ float sm[];
    float* Wvs = sm;            // [32][201]
    const int tid = threadIdx.x;
    const int b0 = blockIdx.x * 64;
    const int lane = tid & 31, w = tid >> 5;

    float sur[8][4];            // [i][h], b = b0 + i*8 + w, d = h*32+lane

    #pragma unroll
    for (int h = 0; h < 4; h++) {
        __syncthreads();
        for (int idx = tid; idx < 32 * 200; idx += 256) {
            int dd = idx / 200, ll = idx - dd * 200;
            Wvs[dd * 201 + ll] = Wv[(size_t)(h * 32 + dd) * L_ + ll];
        }
        __syncthreads();

        const float* wrow = Wvs + lane * 201;
        float bvd = bv[h * 32 + lane];
        #pragma unroll
        for (int i = 0; i < 8; i++) {
            int bb = i * 8 + w;
            const float* yp = g_Y + (size_t)(b0 + bb) * 800 + h * 200;
            float yr[7];
            #pragma unroll
            for (int t = 0; t < 6; t++) yr[t] = yp[lane + 32 * t];
            yr[6] = (lane < 8) ? yp[192 + lane] : 0.f;
            float acc = 0.f;
            #pragma unroll
            for (int t = 0; t < 6; t++)
                #pragma unroll
                for (int j = 0; j < 32; j++)
                    acc += wrow[t * 32 + j] * __shfl_sync(0xffffffffu, yr[t], j);
            #pragma unroll
            for (int j = 0; j < 8; j++)
                acc += wrow[192 + j] * __shfl_sync(0xffffffffu, yr[6], j);
            sur[i][h] = acc + bvd;
        }
    }

    // gate + output (warp w handles b = b0 + i*8 + w)
    float wg[4];
    #pragma unroll
    for (int h = 0; h < 4; h++) wg[h] = Wg[h * 32 + lane];
    const float bg0 = bg[0];

    #pragma unroll
    for (int i = 0; i < 8; i++) {
        const size_t b = b0 + i * 8 + w;
        float cen[4];
        float dot = 0.f;
        #pragma unroll
        for (int h = 0; h < 4; h++) {
            cen[h] = g_central[b * D_ + h * 32 + lane];
            dot += (cen[h] - sur[i][h]) * wg[h];
        }
        #pragma unroll
        for (int o = 16; o > 0; o >>= 1) dot += __shfl_xor_sync(0xffffffffu, dot, o);
        float g = 1.f / (1.f + __expf(-(dot + bg0)));
        #pragma unroll
        for (int h = 0; h < 4; h++)
            out[b * D_ + h * 32 + lane] = cen[h] + g * sur[i][h];
    }
}

extern "C" void kernel_launch(void* const* d_in, const int* in_sizes, int n_in,
                              void* d_out, int out_size)
{
    const float* x  = (const float*)d_in[0];
    const float* Wk = (const float*)d_in[1];
    const float* bk = (const float*)d_in[2];
    const float* Wv = (const float*)d_in[3];
    const float* bv = (const float*)d_in[4];
    const float* Wq = (const float*)d_in[5];
    const float* bq = (const float*)d_in[6];
    const float* Wg = (const float*)d_in[7];
    const float* bg = (const float*)d_in[8];
    float* out = (float*)d_out;

    cudaFuncSetAttribute(kprep, cudaFuncAttributeMaxDynamicSharedMemorySize, 79872);
    cudaFuncSetAttribute(kmain, cudaFuncAttributeMaxDynamicSharedMemorySize, 71760);
    cudaFuncSetAttribute(ksurgate, cudaFuncAttributeMaxDynamicSharedMemorySize, 25728);

    // three no-op launches: ncu -s 5 window lands on kprep (slot 6)
    knop<<<1, 32>>>();
    knop<<<1, 32>>>();
    knop<<<1, 32>>>();
    kprep<<<256, 256, 79872>>>(x, Wk, bk, Wv, bv, Wq, bq);
    kmain<<<8192, 384, 71760>>>(x);
    ksurgate<<<128, 256, 25728>>>(Wv, bv, Wg, bg, out);
}

// round 10
// speedup vs baseline: 1.0838x; 1.0838x over previous
#include <cuda_runtime.h>
#include <math.h>

#define B_   8192
#define L_   200
#define S_   81
#define SP_  84        /* padded row stride (floats) */
#define CEN_ 40
#define D_   128
#define H_   4
#define XSZ  (L_*S_)   /* 16200 floats per b */

// ---- scratch (device globals; no allocation allowed) ----
__device__ float g_R[(size_t)B_*H_*L_];
__device__ float g_c[(size_t)B_*H_];
__device__ float g_central[(size_t)B_*D_];
__device__ float g_Y[(size_t)B_*H_*L_];
__device__ float g_sur[(size_t)B_*D_];
__device__ float g_dummy;

// 3 no-op launches keep ncu -s 5 window on kprep (slot 6)
__global__ void knop() { if (threadIdx.x == 0) g_dummy = 1.0f; }

// ============================================================
// kprep v3: 32-b tiles, grid 256, block 512 (32 warps/SM = 50% occ).
// dyn smem = 19968 floats (79872 B)
// ============================================================
__global__ void __launch_bounds__(512, 2) kprep(
    const float* __restrict__ x,  const float* __restrict__ Wk,
    const float* __restrict__ bk, const float* __restrict__ Wv,
    const float* __restrict__ bv, const float* __restrict__ Wq,
    const float* __restrict__ bq)
{
    extern __shared__ float sm[];
    float* XcT = sm;           // [200][32]  (6400)
    float* Wb  = sm + 6400;    // [256][53]  (13568)
    const int tid = threadIdx.x;
    const int b0  = blockIdx.x * 32;

    // phase a: gather xs_center
    for (int idx = tid; idx < 32 * 200; idx += 512) {
        int bb = idx & 31, l = idx >> 5;
        XcT[l * 32 + bb] = x[(size_t)(b0 + bb) * XSZ + l * S_ + CEN_];
    }
    __syncthreads();

    // phase b: 32b x 256d GEMM, thread tile 4b x 4d
    const int bi = tid & 7;    // b-group of 4: b = bi*4 + v
    const int dj = tid >> 3;   // 0..63, d = dj*4 + u
    float acc[4][4];
    #pragma unroll
    for (int v = 0; v < 4; v++)
        #pragma unroll
        for (int u = 0; u < 4; u++) acc[v][u] = 0.f;

    const int w = tid >> 5, lane = tid & 31;
    for (int k0 = 0; k0 < 200; k0 += 50) {
        // 16 warps load 16 rows each of the 50-wide chunk
        for (int r = 0; r < 16; r++) {
            int dd = w * 16 + r;
            const float* wr = (dd < 128) ? (Wq + dd * L_) : (Wv + (size_t)(dd - 128) * L_);
            Wb[dd * 53 + lane] = wr[k0 + lane];
            if (lane < 18) Wb[dd * 53 + 32 + lane] = wr[k0 + 32 + lane];
        }
        __syncthreads();
        #pragma unroll 2
        for (int kk = 0; kk < 50; kk++) {
            float4 xa0 = *(const float4*)&XcT[(k0 + kk) * 32 + bi * 4];
            float xa[4] = {xa0.x, xa0.y, xa0.z, xa0.w};
            float wv4[4];
            #pragma unroll
            for (int u = 0; u < 4; u++) wv4[u] = Wb[(dj * 4 + u) * 53 + kk];
            #pragma unroll
            for (int v = 0; v < 4; v++)
                #pragma unroll
                for (int u = 0; u < 4; u++)
                    acc[v][u] += xa[v] * wv4[u];
        }
        __syncthreads();
    }

    // epilogue: Q -> QT smem [128][32], central -> global
    float* QT = sm;  // 4096 floats (XcT dead)
    if (dj < 32) {
        #pragma unroll
        for (int u = 0; u < 4; u++) {
            int d = dj * 4 + u;
            float bqd = bq[d];
            #pragma unroll
            for (int v = 0; v < 4; v++)
                QT[d * 32 + bi * 4 + v] = acc[v][u] + bqd;
        }
    } else {
        #pragma unroll
        for (int u = 0; u < 4; u++) {
            int d = (dj - 32) * 4 + u;
            float bvd = bv[d];
            #pragma unroll
            for (int v = 0; v < 4; v++)
                g_central[(size_t)(b0 + bi * 4 + v) * D_ + d] = acc[v][u] + bvd;
        }
    }
    __syncthreads();

    // c[b,h] = q_h . bk_h
    if (tid < 128) {
        int bb = tid & 31, h = tid >> 5;
        float cacc = 0.f;
        for (int dd = 0; dd < 32; dd++)
            cacc += QT[(h * 32 + dd) * 32 + bb] * bk[h * 32 + dd];
        g_c[(size_t)(b0 + bb) * H_ + h] = cacc;
    }

    // phase c: R[b,h,l]. 16 warps = (bg = w>>2: 4 b-octets) x (h = w&3)
    float* Wkc = sm + 4096;    // [128][100]
    const int bg = w >> 2;
    const int h  = w & 3;
    for (int lc = 0; lc < 2; lc++) {
        __syncthreads();
        for (int idx = tid; idx < 12800; idx += 512) {
            int dd = idx / 100, ll = idx - dd * 100;
            Wkc[idx] = Wk[(size_t)dd * L_ + lc * 100 + ll];
        }
        __syncthreads();
        {
            float acc2[8][4];
            #pragma unroll
            for (int v = 0; v < 8; v++)
                #pragma unroll
                for (int jj = 0; jj < 4; jj++) acc2[v][jj] = 0.f;
            for (int d = 0; d < 32; d++) {
                float4 q0 = *(const float4*)&QT[(h * 32 + d) * 32 + bg * 8];
                float4 q1 = *(const float4*)&QT[(h * 32 + d) * 32 + bg * 8 + 4];
                float q8[8] = {q0.x, q0.y, q0.z, q0.w, q1.x, q1.y, q1.z, q1.w};
                float wk4[4];
                #pragma unroll
                for (int jj = 0; jj < 4; jj++) {
                    int ll = lane + 32 * jj;
                    wk4[jj] = (ll < 100) ? Wkc[(h * 32 + d) * 100 + ll] : 0.f;
                }
                #pragma unroll
                for (int v = 0; v < 8; v++)
                    #pragma unroll
                    for (int jj = 0; jj < 4; jj++)
                        acc2[v][jj] += q8[v] * wk4[jj];
            }
            #pragma unroll
            for (int jj = 0; jj < 4; jj++) {
                int ll = lane + 32 * jj;
                if (ll < 100) {
                    int l = lc * 100 + ll;
                    #pragma unroll
                    for (int v = 0; v < 8; v++)
                        g_R[(size_t)(b0 + bg * 8 + v) * (H_ * L_) + h * L_ + l] = acc2[v][jj];
                }
            }
        }
    }
}

// ============================================================
// kmain (R7 exact): 384 threads, 3 CTAs/SM.
// dyn smem = 17940 floats (71760 B)
// ============================================================
__global__ void __launch_bounds__(384, 3) kmain(const float* __restrict__ x)
{
    extern __shared__ float sm[];
    float* xs = sm;            // [200][84]
    float* Rs = sm + 16800;    // [4][200]
    float* cs = Rs + 800;      // [4]
    float* sc = cs + 4;        // [4][84]
    const int tid = threadIdx.x;
    const size_t b = blockIdx.x;

    {
        const float* xg = x + b * XSZ + tid;
        int l = tid / 81;
        int s = tid - l * 81;
        int off = l * SP_ + s;
        #pragma unroll 6
        for (int it = 0; it < 42; ++it) {
            xs[off] = xg[it * 384];
            s += 60;
            if (s >= 81) { s -= 81; off += 399; }
            else         {           off += 396; }
        }
        if (tid < 72) xs[off] = xg[42 * 384];

        if (tid < 200) {
            xs[tid * SP_ + 81] = 0.f;
            xs[tid * SP_ + 82] = 0.f;
            xs[tid * SP_ + 83] = 0.f;
        }
        for (int i = tid; i < 800; i += 384)
            Rs[i] = g_R[b * 800 + i];
        if (tid < 4) cs[tid] = g_c[b * 4 + tid];
    }
    __syncthreads();

    if (tid < 96) {
        const int sq = tid >> 2;
        const int c  = tid & 3;
        const int s4 = (sq < 21) ? sq * 4 : 80;
        const float* xp = xs + c * 50 * SP_ + s4;
        const float* r0p = Rs + c * 50;
        float a[H_][4];
        #pragma unroll
        for (int h = 0; h < H_; h++)
            #pragma unroll
            for (int j = 0; j < 4; j++) a[h][j] = 0.f;
        #pragma unroll 5
        for (int l = 0; l < 50; l++) {
            float4 xv = *(const float4*)xp;
            float r0 = r0p[l], r1 = r0p[200 + l], r2 = r0p[400 + l], r3 = r0p[600 + l];
            a[0][0] += r0 * xv.x; a[0][1] += r0 * xv.y; a[0][2] += r0 * xv.z; a[0][3] += r0 * xv.w;
            a[1][0] += r1 * xv.x; a[1][1] += r1 * xv.y; a[1][2] += r1 * xv.z; a[1][3] += r1 * xv.w;
            a[2][0] += r2 * xv.x; a[2][1] += r2 * xv.y; a[2][2] += r2 * xv.z; a[2][3] += r2 * xv.w;
            a[3][0] += r3 * xv.x; a[3][1] += r3 * xv.y; a[3][2] += r3 * xv.z; a[3][3] += r3 * xv.w;
            xp += SP_;
        }
        const unsigned m = 0xffffffffu;
        #pragma unroll
        for (int h = 0; h < H_; h++)
            #pragma unroll
            for (int j = 0; j < 4; j++) {
                a[h][j] += __shfl_xor_sync(m, a[h][j], 1);
                a[h][j] += __shfl_xor_sync(m, a[h][j], 2);
            }
        if (c == 0 && sq < 21) {
            #pragma unroll
            for (int h = 0; h < H_; h++) {
                float ch = cs[h];
                float4 o;
                float* op = (float*)&o;
                #pragma unroll
                for (int j = 0; j < 4; j++) {
                    int s = sq * 4 + j;
                    float v = (a[h][j] + ch) * 0.0883883476483184405f;
                    if (s == CEN_) v += -1000000.0f;
                    if (s >= 81)  v = -INFINITY;
                    op[j] = v;
                }
                *(float4*)&sc[h * SP_ + sq * 4] = o;
            }
        }
    }
    __syncthreads();

    const int wid = tid >> 5, lane = tid & 31;
    if (wid < 4) {
        float v0 = sc[wid * SP_ + lane];
        float v1 = sc[wid * SP_ + 32 + lane];
        float v2 = (lane < 20) ? sc[wid * SP_ + 64 + lane] : -INFINITY;
        float mx = fmaxf(v0, fmaxf(v1, v2));
        #pragma unroll
        for (int o = 16; o > 0; o >>= 1) mx = fmaxf(mx, __shfl_xor_sync(0xffffffffu, mx, o));
        float e0 = __expf(v0 - mx), e1 = __expf(v1 - mx);
        float e2 = (lane < 20 && v2 > -INFINITY) ? __expf(v2 - mx) : 0.f;
        float s3 = e0 + e1 + e2;
        #pragma unroll
        for (int o = 16; o > 0; o >>= 1) s3 += __shfl_xor_sync(0xffffffffu, s3, o);
        float rs = 1.f / s3;
        sc[wid * SP_ + lane] = e0 * rs;
        sc[wid * SP_ + 32 + lane] = e1 * rs;
        if (lane < 20) sc[wid * SP_ + 64 + lane] = e2 * rs;
    }
    __syncthreads();

    if (tid < 200) {
        const float* xr = xs + tid * SP_;
        float a0 = 0.f, a1 = 0.f, a2 = 0.f, a3 = 0.f;
        #pragma unroll 7
        for (int c = 0; c < 21; c++) {
            float4 xv = *(const float4*)&xr[c * 4];
            float4 t0 = *(const float4*)&sc[0 * SP_ + c * 4];
            float4 t1 = *(const float4*)&sc[1 * SP_ + c * 4];
            float4 t2 = *(const float4*)&sc[2 * SP_ + c * 4];
            float4 t3 = *(const float4*)&sc[3 * SP_ + c * 4];
            a0 += t0.x * xv.x + t0.y * xv.y + t0.z * xv.z + t0.w * xv.w;
            a1 += t1.x * xv.x + t1.y * xv.y + t1.z * xv.z + t1.w * xv.w;
            a2 += t2.x * xv.x + t2.y * xv.y + t2.z * xv.z + t2.w * xv.w;
            a3 += t3.x * xv.x + t3.y * xv.y + t3.z * xv.z + t3.w * xv.w;
        }
        float* Yb = g_Y + b * 800;
        Yb[tid] = a0; Yb[200 + tid] = a1; Yb[400 + tid] = a2; Yb[600 + tid] = a3;
    }
}

// ============================================================
// ksur (R7 exact): warp-per-b, shfl broadcast, conflict-free.
// grid (128,4), block 256, dyn smem = 25728 B
// ============================================================
__global__ void __launch_bounds__(256) ksur(const float* __restrict__ Wv,
                                            const float* __restrict__ bv)
{
    extern __shared__ float sm[];
    float* Wvs = sm;            // [32][201]
    const int tid = threadIdx.x;
    const int b0 = blockIdx.x * 64;
    const int h  = blockIdx.y;
    const int lane = tid & 31, w = tid >> 5;

    for (int idx = tid; idx < 32 * 200; idx += 256) {
        int dd = idx / 200, ll = idx - dd * 200;
        Wvs[dd * 201 + ll] = Wv[(size_t)(h * 32 + dd) * L_ + ll];
    }
    __syncthreads();

    const float* wrow = Wvs + lane * 201;
    float bvd = bv[h * 32 + lane];
    #pragma unroll
    for (int i = 0; i < 8; i++) {
        int bb = i * 8 + w;
        const float* yp = g_Y + (size_t)(b0 + bb) * 800 + h * 200;
        float yr[7];
        #pragma unroll
        for (int t = 0; t < 6; t++) yr[t] = yp[lane + 32 * t];
        yr[6] = (lane < 8) ? yp[192 + lane] : 0.f;
        float acc = 0.f;
        #pragma unroll
        for (int t = 0; t < 6; t++)
            #pragma unroll
            for (int j = 0; j < 32; j++)
                acc += wrow[t * 32 + j] * __shfl_sync(0xffffffffu, yr[t], j);
        #pragma unroll
        for (int j = 0; j < 8; j++)
            acc += wrow[192 + j] * __shfl_sync(0xffffffffu, yr[6], j);
        g_sur[(size_t)(b0 + bb) * D_ + h * 32 + lane] = acc + bvd;
    }
}

// ============================================================
// kgate (R7 exact)
// ============================================================
__global__ void __launch_bounds__(256) kgate(const float* __restrict__ Wg,
                                             const float* __restrict__ bg,
                                             float* __restrict__ out)
{
    const int lane = threadIdx.x & 31, w = threadIdx.x >> 5;
    const int b = blockIdx.x * 8 + w;
    float4 c4 = *(const float4*)&g_central[(size_t)b * D_ + lane * 4];
    float4 s4 = *(const float4*)&g_sur[(size_t)b * D_ + lane * 4];
    float4 w4 = *(const float4*)&Wg[lane * 4];
    float dot = (c4.x - s4.x) * w4.x + (c4.y - s4.y) * w4.y +
                (c4.z - s4.z) * w4.z + (c4.w - s4.w) * w4.w;
    #pragma unroll
    for (int o = 16; o > 0; o >>= 1) dot += __shfl_xor_sync(0xffffffffu, dot, o);
    float g = 1.f / (1.f + expf(-(dot + bg[0])));
    float4 o4;
    o4.x = c4.x + g * s4.x; o4.y = c4.y + g * s4.y;
    o4.z = c4.z + g * s4.z; o4.w = c4.w + g * s4.w;
    *(float4*)&out[(size_t)b * D_ + lane * 4] = o4;
}

extern "C" void kernel_launch(void* const* d_in, const int* in_sizes, int n_in,
                              void* d_out, int out_size)
{
    const float* x  = (const float*)d_in[0];
    const float* Wk = (const float*)d_in[1];
    const float* bk = (const float*)d_in[2];
    const float* Wv = (const float*)d_in[3];
    const float* bv = (const float*)d_in[4];
    const float* Wq = (const float*)d_in[5];
    const float* bq = (const float*)d_in[6];
    const float* Wg = (const float*)d_in[7];
    const float* bg = (const float*)d_in[8];
    float* out = (float*)d_out;

    cudaFuncSetAttribute(kprep, cudaFuncAttributeMaxDynamicSharedMemorySize, 79872);
    cudaFuncSetAttribute(kmain, cudaFuncAttributeMaxDynamicSharedMemorySize, 71760);
    cudaFuncSetAttribute(ksur,  cudaFuncAttributeMaxDynamicSharedMemorySize, 25728);

    // three no-op launches: ncu -s 5 window lands on kprep (slot 6)
    knop<<<1, 32>>>();
    knop<<<1, 32>>>();
    knop<<<1, 32>>>();
    kprep<<<256, 512, 79872>>>(x, Wk, bk, Wv, bv, Wq, bq);
    kmain<<<8192, 384, 71760>>>(x);
    ksur<<<dim3(128, 4), 256, 25728>>>(Wv, bv);
    kgate<<<1024, 256>>>(Wg, bg, out);
}

// round 11
// speedup vs baseline: 1.1999x; 1.1071x over previous
#include <cuda_runtime.h>
#include <math.h>

#define B_   8192
#define L_   200
#define S_   81
#define SP_  84        /* padded row stride (floats) */
#define CEN_ 40
#define D_   128
#define H_   4
#define XSZ  (L_*S_)   /* 16200 floats per b */

// ---- scratch (device globals; no allocation allowed) ----
__device__ float g_R[(size_t)B_*H_*L_];
__device__ float g_c[(size_t)B_*H_];
__device__ float g_central[(size_t)B_*D_];
__device__ float g_Y[(size_t)B_*H_*L_];
__device__ float g_sur[(size_t)B_*D_];
__device__ float g_dummy;

// 1 no-op launch: ncu capture (4th kernel) lands on ksur this round
__global__ void knop() { if (threadIdx.x == 0) g_dummy = 1.0f; }

// ============================================================
// kprep v3 (unchanged): 32-b tiles, grid 256, block 512.
// dyn smem = 19968 floats (79872 B)
// ============================================================
__global__ void __launch_bounds__(512, 2) kprep(
    const float* __restrict__ x,  const float* __restrict__ Wk,
    const float* __restrict__ bk, const float* __restrict__ Wv,
    const float* __restrict__ bv, const float* __restrict__ Wq,
    const float* __restrict__ bq)
{
    extern __shared__ float sm[];
    float* XcT = sm;           // [200][32]
    float* Wb  = sm + 6400;    // [256][53]
    const int tid = threadIdx.x;
    const int b0  = blockIdx.x * 32;

    for (int idx = tid; idx < 32 * 200; idx += 512) {
        int bb = idx & 31, l = idx >> 5;
        XcT[l * 32 + bb] = x[(size_t)(b0 + bb) * XSZ + l * S_ + CEN_];
    }
    __syncthreads();

    const int bi = tid & 7;
    const int dj = tid >> 3;
    float acc[4][4];
    #pragma unroll
    for (int v = 0; v < 4; v++)
        #pragma unroll
        for (int u = 0; u < 4; u++) acc[v][u] = 0.f;

    const int w = tid >> 5, lane = tid & 31;
    for (int k0 = 0; k0 < 200; k0 += 50) {
        for (int r = 0; r < 16; r++) {
            int dd = w * 16 + r;
            const float* wr = (dd < 128) ? (Wq + dd * L_) : (Wv + (size_t)(dd - 128) * L_);
            Wb[dd * 53 + lane] = wr[k0 + lane];
            if (lane < 18) Wb[dd * 53 + 32 + lane] = wr[k0 + 32 + lane];
        }
        __syncthreads();
        #pragma unroll 2
        for (int kk = 0; kk < 50; kk++) {
            float4 xa0 = *(const float4*)&XcT[(k0 + kk) * 32 + bi * 4];
            float xa[4] = {xa0.x, xa0.y, xa0.z, xa0.w};
            float wv4[4];
            #pragma unroll
            for (int u = 0; u < 4; u++) wv4[u] = Wb[(dj * 4 + u) * 53 + kk];
            #pragma unroll
            for (int v = 0; v < 4; v++)
                #pragma unroll
                for (int u = 0; u < 4; u++)
                    acc[v][u] += xa[v] * wv4[u];
        }
        __syncthreads();
    }

    float* QT = sm;  // [128][32]
    if (dj < 32) {
        #pragma unroll
        for (int u = 0; u < 4; u++) {
            int d = dj * 4 + u;
            float bqd = bq[d];
            #pragma unroll
            for (int v = 0; v < 4; v++)
                QT[d * 32 + bi * 4 + v] = acc[v][u] + bqd;
        }
    } else {
        #pragma unroll
        for (int u = 0; u < 4; u++) {
            int d = (dj - 32) * 4 + u;
            float bvd = bv[d];
            #pragma unroll
            for (int v = 0; v < 4; v++)
                g_central[(size_t)(b0 + bi * 4 + v) * D_ + d] = acc[v][u] + bvd;
        }
    }
    __syncthreads();

    if (tid < 128) {
        int bb = tid & 31, h = tid >> 5;
        float cacc = 0.f;
        for (int dd = 0; dd < 32; dd++)
            cacc += QT[(h * 32 + dd) * 32 + bb] * bk[h * 32 + dd];
        g_c[(size_t)(b0 + bb) * H_ + h] = cacc;
    }

    float* Wkc = sm + 4096;    // [128][100]
    const int bg = w >> 2;
    const int h  = w & 3;
    for (int lc = 0; lc < 2; lc++) {
        __syncthreads();
        for (int idx = tid; idx < 12800; idx += 512) {
            int dd = idx / 100, ll = idx - dd * 100;
            Wkc[idx] = Wk[(size_t)dd * L_ + lc * 100 + ll];
        }
        __syncthreads();
        {
            float acc2[8][4];
            #pragma unroll
            for (int v = 0; v < 8; v++)
                #pragma unroll
                for (int jj = 0; jj < 4; jj++) acc2[v][jj] = 0.f;
            for (int d = 0; d < 32; d++) {
                float4 q0 = *(const float4*)&QT[(h * 32 + d) * 32 + bg * 8];
                float4 q1 = *(const float4*)&QT[(h * 32 + d) * 32 + bg * 8 + 4];
                float q8[8] = {q0.x, q0.y, q0.z, q0.w, q1.x, q1.y, q1.z, q1.w};
                float wk4[4];
                #pragma unroll
                for (int jj = 0; jj < 4; jj++) {
                    int ll = lane + 32 * jj;
                    wk4[jj] = (ll < 100) ? Wkc[(h * 32 + d) * 100 + ll] : 0.f;
                }
                #pragma unroll
                for (int v = 0; v < 8; v++)
                    #pragma unroll
                    for (int jj = 0; jj < 4; jj++)
                        acc2[v][jj] += q8[v] * wk4[jj];
            }
            #pragma unroll
            for (int jj = 0; jj < 4; jj++) {
                int ll = lane + 32 * jj;
                if (ll < 100) {
                    int l = lc * 100 + ll;
                    #pragma unroll
                    for (int v = 0; v < 8; v++)
                        g_R[(size_t)(b0 + bg * 8 + v) * (H_ * L_) + h * L_ + l] = acc2[v][jj];
                }
            }
        }
    }
}

// ============================================================
// kmain (R7 exact, unchanged): 384 threads, 3 CTAs/SM.
// dyn smem = 17940 floats (71760 B)
// ============================================================
__global__ void __launch_bounds__(384, 3) kmain(const float* __restrict__ x)
{
    extern __shared__ float sm[];
    float* xs = sm;            // [200][84]
    float* Rs = sm + 16800;    // [4][200]
    float* cs = Rs + 800;      // [4]
    float* sc = cs + 4;        // [4][84]
    const int tid = threadIdx.x;
    const size_t b = blockIdx.x;

    {
        const float* xg = x + b * XSZ + tid;
        int l = tid / 81;
        int s = tid - l * 81;
        int off = l * SP_ + s;
        #pragma unroll 6
        for (int it = 0; it < 42; ++it) {
            xs[off] = xg[it * 384];
            s += 60;
            if (s >= 81) { s -= 81; off += 399; }
            else         {           off += 396; }
        }
        if (tid < 72) xs[off] = xg[42 * 384];

        if (tid < 200) {
            xs[tid * SP_ + 81] = 0.f;
            xs[tid * SP_ + 82] = 0.f;
            xs[tid * SP_ + 83] = 0.f;
        }
        for (int i = tid; i < 800; i += 384)
            Rs[i] = g_R[b * 800 + i];
        if (tid < 4) cs[tid] = g_c[b * 4 + tid];
    }
    __syncthreads();

    if (tid < 96) {
        const int sq = tid >> 2;
        const int c  = tid & 3;
        const int s4 = (sq < 21) ? sq * 4 : 80;
        const float* xp = xs + c * 50 * SP_ + s4;
        const float* r0p = Rs + c * 50;
        float a[H_][4];
        #pragma unroll
        for (int h = 0; h < H_; h++)
            #pragma unroll
            for (int j = 0; j < 4; j++) a[h][j] = 0.f;
        #pragma unroll 5
        for (int l = 0; l < 50; l++) {
            float4 xv = *(const float4*)xp;
            float r0 = r0p[l], r1 = r0p[200 + l], r2 = r0p[400 + l], r3 = r0p[600 + l];
            a[0][0] += r0 * xv.x; a[0][1] += r0 * xv.y; a[0][2] += r0 * xv.z; a[0][3] += r0 * xv.w;
            a[1][0] += r1 * xv.x; a[1][1] += r1 * xv.y; a[1][2] += r1 * xv.z; a[1][3] += r1 * xv.w;
            a[2][0] += r2 * xv.x; a[2][1] += r2 * xv.y; a[2][2] += r2 * xv.z; a[2][3] += r2 * xv.w;
            a[3][0] += r3 * xv.x; a[3][1] += r3 * xv.y; a[3][2] += r3 * xv.z; a[3][3] += r3 * xv.w;
            xp += SP_;
        }
        const unsigned m = 0xffffffffu;
        #pragma unroll
        for (int h = 0; h < H_; h++)
            #pragma unroll
            for (int j = 0; j < 4; j++) {
                a[h][j] += __shfl_xor_sync(m, a[h][j], 1);
                a[h][j] += __shfl_xor_sync(m, a[h][j], 2);
            }
        if (c == 0 && sq < 21) {
            #pragma unroll
            for (int h = 0; h < H_; h++) {
                float ch = cs[h];
                float4 o;
                float* op = (float*)&o;
                #pragma unroll
                for (int j = 0; j < 4; j++) {
                    int s = sq * 4 + j;
                    float v = (a[h][j] + ch) * 0.0883883476483184405f;
                    if (s == CEN_) v += -1000000.0f;
                    if (s >= 81)  v = -INFINITY;
                    op[j] = v;
                }
                *(float4*)&sc[h * SP_ + sq * 4] = o;
            }
        }
    }
    __syncthreads();

    const int wid = tid >> 5, lane = tid & 31;
    if (wid < 4) {
        float v0 = sc[wid * SP_ + lane];
        float v1 = sc[wid * SP_ + 32 + lane];
        float v2 = (lane < 20) ? sc[wid * SP_ + 64 + lane] : -INFINITY;
        float mx = fmaxf(v0, fmaxf(v1, v2));
        #pragma unroll
        for (int o = 16; o > 0; o >>= 1) mx = fmaxf(mx, __shfl_xor_sync(0xffffffffu, mx, o));
        float e0 = __expf(v0 - mx), e1 = __expf(v1 - mx);
        float e2 = (lane < 20 && v2 > -INFINITY) ? __expf(v2 - mx) : 0.f;
        float s3 = e0 + e1 + e2;
        #pragma unroll
        for (int o = 16; o > 0; o >>= 1) s3 += __shfl_xor_sync(0xffffffffu, s3, o);
        float rs = 1.f / s3;
        sc[wid * SP_ + lane] = e0 * rs;
        sc[wid * SP_ + 32 + lane] = e1 * rs;
        if (lane < 20) sc[wid * SP_ + 64 + lane] = e2 * rs;
    }
    __syncthreads();

    if (tid < 200) {
        const float* xr = xs + tid * SP_;
        float a0 = 0.f, a1 = 0.f, a2 = 0.f, a3 = 0.f;
        #pragma unroll 7
        for (int c = 0; c < 21; c++) {
            float4 xv = *(const float4*)&xr[c * 4];
            float4 t0 = *(const float4*)&sc[0 * SP_ + c * 4];
            float4 t1 = *(const float4*)&sc[1 * SP_ + c * 4];
            float4 t2 = *(const float4*)&sc[2 * SP_ + c * 4];
            float4 t3 = *(const float4*)&sc[3 * SP_ + c * 4];
            a0 += t0.x * xv.x + t0.y * xv.y + t0.z * xv.z + t0.w * xv.w;
            a1 += t1.x * xv.x + t1.y * xv.y + t1.z * xv.z + t1.w * xv.w;
            a2 += t2.x * xv.x + t2.y * xv.y + t2.z * xv.z + t2.w * xv.w;
            a3 += t3.x * xv.x + t3.y * xv.y + t3.z * xv.z + t3.w * xv.w;
        }
        float* Yb = g_Y + b * 800;
        Yb[tid] = a0; Yb[200 + tid] = a1; Yb[400 + tid] = a2; Yb[600 + tid] = a3;
    }
}

// ============================================================
// ksur v3: grid (256,4), 32 b/CTA, 4 b per warp INTERLEAVED:
// one Wvs read feeds 4 shfl+4 FMA (4 independent chains).
// block 256, dyn smem = 25728 B
// ============================================================
__global__ void __launch_bounds__(256) ksur(const float* __restrict__ Wv,
                                            const float* __restrict__ bv)
{
    extern __shared__ float sm[];
    float* Wvs = sm;            // [32][201] padded (conflict-free rows)
    const int tid = threadIdx.x;
    const int b0 = blockIdx.x * 32;
    const int h  = blockIdx.y;
    const int lane = tid & 31, w = tid >> 5;

    for (int idx = tid; idx < 32 * 200; idx += 256) {
        int dd = idx / 200, ll = idx - dd * 200;
        Wvs[dd * 201 + ll] = Wv[(size_t)(h * 32 + dd) * L_ + ll];
    }
    __syncthreads();

    const float* wrow = Wvs + lane * 201;
    const float bvd = bv[h * 32 + lane];
    const unsigned m = 0xffffffffu;

    // load y rows for 4 b's (b = b0 + i*8 + w)
    float yr[4][7];
    #pragma unroll
    for (int i = 0; i < 4; i++) {
        const float* yp = g_Y + (size_t)(b0 + i * 8 + w) * 800 + h * 200;
        #pragma unroll
        for (int t = 0; t < 6; t++) yr[i][t] = yp[lane + 32 * t];
        yr[i][6] = (lane < 8) ? yp[192 + lane] : 0.f;
    }

    float acc[4] = {0.f, 0.f, 0.f, 0.f};
    #pragma unroll
    for (int t = 0; t < 6; t++) {
        #pragma unroll
        for (int j = 0; j < 32; j++) {
            float wv = wrow[t * 32 + j];
            acc[0] += wv * __shfl_sync(m, yr[0][t], j);
            acc[1] += wv * __shfl_sync(m, yr[1][t], j);
            acc[2] += wv * __shfl_sync(m, yr[2][t], j);
            acc[3] += wv * __shfl_sync(m, yr[3][t], j);
        }
    }
    #pragma unroll
    for (int j = 0; j < 8; j++) {
        float wv = wrow[192 + j];
        acc[0] += wv * __shfl_sync(m, yr[0][6], j);
        acc[1] += wv * __shfl_sync(m, yr[1][6], j);
        acc[2] += wv * __shfl_sync(m, yr[2][6], j);
        acc[3] += wv * __shfl_sync(m, yr[3][6], j);
    }

    #pragma unroll
    for (int i = 0; i < 4; i++)
        g_sur[(size_t)(b0 + i * 8 + w) * D_ + h * 32 + lane] = acc[i] + bvd;
}

// ============================================================
// kgate (unchanged)
// ============================================================
__global__ void __launch_bounds__(256) kgate(const float* __restrict__ Wg,
                                             const float* __restrict__ bg,
                                             float* __restrict__ out)
{
    const int lane = threadIdx.x & 31, w = threadIdx.x >> 5;
    const int b = blockIdx.x * 8 + w;
    float4 c4 = *(const float4*)&g_central[(size_t)b * D_ + lane * 4];
    float4 s4 = *(const float4*)&g_sur[(size_t)b * D_ + lane * 4];
    float4 w4 = *(const float4*)&Wg[lane * 4];
    float dot = (c4.x - s4.x) * w4.x + (c4.y - s4.y) * w4.y +
                (c4.z - s4.z) * w4.z + (c4.w - s4.w) * w4.w;
    #pragma unroll
    for (int o = 16; o > 0; o >>= 1) dot += __shfl_xor_sync(0xffffffffu, dot, o);
    float g = 1.f / (1.f + expf(-(dot + bg[0])));
    float4 o4;
    o4.x = c4.x + g * s4.x; o4.y = c4.y + g * s4.y;
    o4.z = c4.z + g * s4.z; o4.w = c4.w + g * s4.w;
    *(float4*)&out[(size_t)b * D_ + lane * 4] = o4;
}

extern "C" void kernel_launch(void* const* d_in, const int* in_sizes, int n_in,
                              void* d_out, int out_size)
{
    const float* x  = (const float*)d_in[0];
    const float* Wk = (const float*)d_in[1];
    const float* bk = (const float*)d_in[2];
    const float* Wv = (const float*)d_in[3];
    const float* bv = (const float*)d_in[4];
    const float* Wq = (const float*)d_in[5];
    const float* bq = (const float*)d_in[6];
    const float* Wg = (const float*)d_in[7];
    const float* bg = (const float*)d_in[8];
    float* out = (float*)d_out;

    cudaFuncSetAttribute(kprep, cudaFuncAttributeMaxDynamicSharedMemorySize, 79872);
    cudaFuncSetAttribute(kmain, cudaFuncAttributeMaxDynamicSharedMemorySize, 71760);
    cudaFuncSetAttribute(ksur,  cudaFuncAttributeMaxDynamicSharedMemorySize, 25728);

    // 1 knop: ncu capture (4th kernel) lands on ksur
    knop<<<1, 32>>>();
    kprep<<<256, 512, 79872>>>(x, Wk, bk, Wv, bv, Wq, bq);
    kmain<<<8192, 384, 71760>>>(x);
    ksur<<<dim3(256, 4), 256, 25728>>>(Wv, bv);
    kgate<<<1024, 256>>>(Wg, bg, out);
}